// round 9
// baseline (speedup 1.0000x reference)
#include <cuda_runtime.h>

#define NN 512          // total nodes
#define FF 512          // feature dim
#define HH 512          // hidden dim
#define RR 4            // relations
#define LN_EPS 1e-5f
#define THRESH 0.2f

typedef unsigned long long ull;

// Scratch (device globals: no allocation allowed in kernel_launch)
__device__ float g_a[RR][NN][HH];   // x @ Wl[r]^T + b1[r]
__device__ float g_b[RR][NN][HH];   // x @ Wr[r]^T
__device__ float g_sa[RR][NN];      // row sums of g_a
__device__ float g_qa[RR][NN];      // row sumsq of g_a
__device__ float g_sb[RR][NN];      // row sums of g_b
__device__ float g_qb[RR][NN];      // row sumsq of g_b

// ---------------------------------------------------------------------------
// packed f32x2 helpers
// ---------------------------------------------------------------------------
__device__ __forceinline__ ull add2(ull a, ull b) {
    ull d; asm("add.rn.f32x2 %0,%1,%2;" : "=l"(d) : "l"(a), "l"(b)); return d;
}
__device__ __forceinline__ ull fma2(ull a, ull b, ull c) {
    ull d; asm("fma.rn.f32x2 %0,%1,%2,%3;" : "=l"(d) : "l"(a), "l"(b), "l"(c)); return d;
}
__device__ __forceinline__ ull bcast2(float x) {
    ull d; unsigned u = __float_as_uint(x);
    asm("mov.b64 %0,{%1,%1};" : "=l"(d) : "r"(u)); return d;
}
__device__ __forceinline__ float sum2(ull v) {
    unsigned lo, hi;
    asm("mov.b64 {%0,%1},%2;" : "=r"(lo), "=r"(hi) : "l"(v));
    return __uint_as_float(lo) + __uint_as_float(hi);
}
__device__ __forceinline__ ull relu2(ull v) {
    unsigned lo, hi;
    asm("mov.b64 {%0,%1},%2;" : "=r"(lo), "=r"(hi) : "l"(v));
    float flo = fmaxf(__uint_as_float(lo), 0.f);
    float fhi = fmaxf(__uint_as_float(hi), 0.f);
    ull d;
    asm("mov.b64 %0,{%1,%2};" : "=l"(d) : "r"(__float_as_uint(flo)), "r"(__float_as_uint(fhi)));
    return d;
}

// ---------------------------------------------------------------------------
// Kernel 0: concat feats_img/feats_txt into out[0 : NN*FF]
// ---------------------------------------------------------------------------
__global__ void concat_kernel(const float* __restrict__ img,
                              const float* __restrict__ txt,
                              float* __restrict__ out) {
    int idx = blockIdx.x * blockDim.x + threadIdx.x;
    const int HALF = 256 * FF / 4;
    float4 v;
    if (idx < HALF) v = reinterpret_cast<const float4*>(img)[idx];
    else            v = reinterpret_cast<const float4*>(txt)[idx - HALF];
    reinterpret_cast<float4*>(out)[idx] = v;
}

// ---------------------------------------------------------------------------
// Kernel 1: projection SGEMM (BM=BN=128, BK=8, 8x8/thread, packed f32x2),
// double-buffered smem, one sync per k-step.
// ---------------------------------------------------------------------------
__global__ __launch_bounds__(256) void gemm_ab(const float* __restrict__ x,
                                               const float* __restrict__ W1,
                                               const float* __restrict__ b1) {
    const int r    = blockIdx.z >> 1;
    const int side = blockIdx.z & 1;
    const float* B = W1 + (size_t)r * HH * (2 * FF) + side * FF;
    float* outp = side ? &g_b[r][0][0] : &g_a[r][0][0];

    const int bi = blockIdx.y * 128;
    const int bh = blockIdx.x * 128;

    __shared__ __align__(16) float As[2][8][128];
    __shared__ __align__(16) float Bs[2][8][128];

    const int tid  = threadIdx.x;
    const int lrow = tid >> 1;
    const int lcol = (tid & 1) << 2;
    const int ty   = tid >> 4;
    const int tx   = tid & 15;

    const float* aptr = x + (size_t)(bi + lrow) * FF + lcol;
    const float* bptr = B + (size_t)(bh + lrow) * (2 * FF) + lcol;

    ull acc2[8][4];
#pragma unroll
    for (int m = 0; m < 8; m++)
#pragma unroll
        for (int n = 0; n < 4; n++) acc2[m][n] = 0ull;

    {
        float4 av = *reinterpret_cast<const float4*>(aptr);
        float4 bv = *reinterpret_cast<const float4*>(bptr);
        As[0][lcol + 0][lrow] = av.x; As[0][lcol + 1][lrow] = av.y;
        As[0][lcol + 2][lrow] = av.z; As[0][lcol + 3][lrow] = av.w;
        Bs[0][lcol + 0][lrow] = bv.x; Bs[0][lcol + 1][lrow] = bv.y;
        Bs[0][lcol + 2][lrow] = bv.z; Bs[0][lcol + 3][lrow] = bv.w;
    }
    __syncthreads();

#pragma unroll 1
    for (int k0 = 0; k0 < FF / 8; k0++) {
        const int cur = k0 & 1;
        float4 av, bv;
        if (k0 < FF / 8 - 1) {
            av = *reinterpret_cast<const float4*>(aptr + (k0 + 1) * 8);
            bv = *reinterpret_cast<const float4*>(bptr + (k0 + 1) * 8);
        }
#pragma unroll
        for (int kk = 0; kk < 8; kk++) {
            float4 a0 = *reinterpret_cast<const float4*>(&As[cur][kk][ty * 8]);
            float4 a1 = *reinterpret_cast<const float4*>(&As[cur][kk][ty * 8 + 4]);
            ulonglong2 b0 = *reinterpret_cast<const ulonglong2*>(&Bs[cur][kk][tx * 8]);
            ulonglong2 b1v = *reinterpret_cast<const ulonglong2*>(&Bs[cur][kk][tx * 8 + 4]);
            ull rb2[4] = {b0.x, b0.y, b1v.x, b1v.y};
            float ra[8] = {a0.x, a0.y, a0.z, a0.w, a1.x, a1.y, a1.z, a1.w};
#pragma unroll
            for (int m = 0; m < 8; m++) {
                ull ra2 = bcast2(ra[m]);
#pragma unroll
                for (int n = 0; n < 4; n++)
                    acc2[m][n] = fma2(ra2, rb2[n], acc2[m][n]);
            }
        }
        if (k0 < FF / 8 - 1) {
            const int nxt = cur ^ 1;
            As[nxt][lcol + 0][lrow] = av.x; As[nxt][lcol + 1][lrow] = av.y;
            As[nxt][lcol + 2][lrow] = av.z; As[nxt][lcol + 3][lrow] = av.w;
            Bs[nxt][lcol + 0][lrow] = bv.x; Bs[nxt][lcol + 1][lrow] = bv.y;
            Bs[nxt][lcol + 2][lrow] = bv.z; Bs[nxt][lcol + 3][lrow] = bv.w;
        }
        __syncthreads();
    }

    ull bias2[4];
    if (side) {
#pragma unroll
        for (int n = 0; n < 4; n++) bias2[n] = 0ull;
    } else {
        const ull* bp = reinterpret_cast<const ull*>(b1 + r * HH + bh + tx * 8);
#pragma unroll
        for (int n = 0; n < 4; n++) bias2[n] = bp[n];
    }
#pragma unroll
    for (int m = 0; m < 8; m++) {
        ull* orow = reinterpret_cast<ull*>(outp + (size_t)(bi + ty * 8 + m) * HH + bh + tx * 8);
#pragma unroll
        for (int n = 0; n < 4; n++)
            orow[n] = add2(acc2[m][n], bias2[n]);
    }
}

// ---------------------------------------------------------------------------
// Kernel 1b: row sums + sums of squares of g_a / g_b (one warp per row).
// ---------------------------------------------------------------------------
__global__ __launch_bounds__(256) void rowsumsq_kernel() {
    int gw   = (blockIdx.x * 256 + threadIdx.x) >> 5;   // 0..4095
    int lane = threadIdx.x & 31;
    int side = gw >> 11;            // 0: a, 1: b
    int rem  = gw & 2047;           // r*NN + node
    const float* base = side ? &g_b[0][0][0] : &g_a[0][0][0];
    const float* row  = base + (size_t)rem * HH;

    float s = 0.f, q = 0.f;
#pragma unroll
    for (int c = 0; c < 4; c++) {
        float4 v = *reinterpret_cast<const float4*>(row + c * 128 + lane * 4);
        s += (v.x + v.y) + (v.z + v.w);
        q = fmaf(v.x, v.x, q); q = fmaf(v.y, v.y, q);
        q = fmaf(v.z, v.z, q); q = fmaf(v.w, v.w, q);
    }
#pragma unroll
    for (int o = 16; o > 0; o >>= 1) {
        s += __shfl_xor_sync(0xffffffffu, s, o);
        q += __shfl_xor_sync(0xffffffffu, q, o);
    }
    if (lane == 0) {
        if (side) { g_sb[0][rem] = s; g_qb[0][rem] = q; }
        else      { g_sa[0][rem] = s; g_qa[0][rem] = q; }
    }
}

// ---------------------------------------------------------------------------
// Kernel 2: pairwise LN-MLP + argmax. Two passes per r over smem tiles.
// Tile 64i x 32j, 512 threads, thread owns 2i x 2j = 4 pairs.
// Warp footprint: 8 ty x 4 tx  ->  A loads 1 wavefront (8 rows span all 32
// banks at stride 516), B loads 1 wavefront (4 rows, 64B), params broadcast.
// Inner loops: 2 c-slots/iter, split accumulator banks (8 indep chains).
// ---------------------------------------------------------------------------
#define PBI 64
#define PBJ 32
#define PPAD 4
#define PST (HH + PPAD)        // 516 floats per row
#define PSMEM_FLOATS ((PBI + PBJ) * PST + 3 * (HH + 4) + 4)
#define PSMEM_BYTES (PSMEM_FLOATS * 4)
#define PTHREADS 512

__global__ __launch_bounds__(PTHREADS) void pairwise_kernel(
        const float* __restrict__ gamma, const float* __restrict__ beta,
        const float* __restrict__ w2,    const float* __restrict__ b2,
        float* __restrict__ out) {
    extern __shared__ __align__(16) float sm[];
    float* sa  = sm;                        // PBI * PST
    float* sb  = sa + PBI * PST;            // PBJ * PST
    float* sg  = sb + PBJ * PST;            // HH + 4
    float* sbe = sg + (HH + 4);             // HH + 4
    float* sw  = sbe + (HH + 4);            // HH + 4

    const int tid  = threadIdx.x;
    const int lane = tid & 31;
    const int wrp  = tid >> 5;              // 0..15
    // warp covers 8 consecutive ty values and 4 consecutive tx values
    const int ty = (lane >> 2) + ((wrp & 3) << 3);    // 0..31
    const int tx = (lane & 3) + ((wrp >> 2) << 2);    // 0..15
    const int bi0 = blockIdx.y * PBI;
    const int bj0 = blockIdx.x * PBJ;

    float best[4];
    int   bestr[4];
#pragma unroll
    for (int p = 0; p < 4; p++) { best[p] = -1e30f; bestr[p] = 0; }

    const float inv_h = 1.f / (float)HH;

#pragma unroll 1
    for (int r = 0; r < RR; r++) {
        __syncthreads();
        // stage tiles: (PBI+PBJ)*HH/4 = 12288 float4 over 512 threads
        for (int t = tid; t < (PBI + PBJ) * (HH / 4); t += PTHREADS) {
            int row = t >> 7;
            int c4  = t & 127;
            float4 v;
            float* dst;
            if (row < PBI) {
                v = reinterpret_cast<const float4*>(&g_a[r][bi0 + row][0])[c4];
                dst = &sa[row * PST];
            } else {
                v = reinterpret_cast<const float4*>(&g_b[r][bj0 + row - PBI][0])[c4];
                dst = &sb[(row - PBI) * PST];
            }
            reinterpret_cast<float4*>(dst)[c4] = v;
        }
        if (tid < 3 * HH / 4) {
            int arr = tid >> 7;
            int c4  = tid & 127;
            const float* src = (arr == 0) ? gamma : (arr == 1) ? beta : w2;
            float* dst = (arr == 0) ? sg : (arr == 1) ? sbe : sw;
            reinterpret_cast<float4*>(dst)[c4] =
                reinterpret_cast<const float4*>(src + r * HH)[c4];
        }
        __syncthreads();

        const ulonglong2* pA[2];
        const ulonglong2* pB[2];
#pragma unroll
        for (int p = 0; p < 2; p++)
            pA[p] = reinterpret_cast<const ulonglong2*>(&sa[(ty + 32 * p) * PST]);
#pragma unroll
        for (int q = 0; q < 2; q++)
            pB[q] = reinterpret_cast<const ulonglong2*>(&sb[(tx + 16 * q) * PST]);

        // ---- pass 1: cross terms, 2 slots/iter, 8 independent chains ----
        ull crA[4] = {0ull, 0ull, 0ull, 0ull};
        ull crB[4] = {0ull, 0ull, 0ull, 0ull};
#pragma unroll 2
        for (int c = 0; c < HH / 4; c += 2) {
            ulonglong2 Aa[2], Ba[2], Ab[2], Bb[2];
#pragma unroll
            for (int p = 0; p < 2; p++) { Aa[p] = pA[p][c]; Ab[p] = pA[p][c + 1]; }
#pragma unroll
            for (int q = 0; q < 2; q++) { Ba[q] = pB[q][c]; Bb[q] = pB[q][c + 1]; }
#pragma unroll
            for (int p = 0; p < 2; p++)
#pragma unroll
                for (int q = 0; q < 2; q++) {
                    int idx = p * 2 + q;
                    crA[idx] = fma2(Aa[p].x, Ba[q].x, crA[idx]);
                    crA[idx] = fma2(Aa[p].y, Ba[q].y, crA[idx]);
                    crB[idx] = fma2(Ab[p].x, Bb[q].x, crB[idx]);
                    crB[idx] = fma2(Ab[p].y, Bb[q].y, crB[idx]);
                }
        }

        // ---- LN constants (closed form, no reductions) ----
        ull al[4], de[4];
        {
            float SA[2], QA[2], SB[2], QB[2];
#pragma unroll
            for (int p = 0; p < 2; p++) {
                SA[p] = g_sa[r][bi0 + ty + 32 * p];
                QA[p] = g_qa[r][bi0 + ty + 32 * p];
            }
#pragma unroll
            for (int q = 0; q < 2; q++) {
                SB[q] = g_sb[r][bj0 + tx + 16 * q];
                QB[q] = g_qb[r][bj0 + tx + 16 * q];
            }
#pragma unroll
            for (int p = 0; p < 2; p++)
#pragma unroll
                for (int q = 0; q < 2; q++) {
                    int idx = p * 2 + q;
                    float cross = sum2(add2(crA[idx], crB[idx]));
                    float mu  = (SA[p] + SB[q]) * inv_h;
                    float e2  = fmaf(2.f, cross, QA[p] + QB[q]) * inv_h;
                    float var = fmaf(-mu, mu, e2);
                    float rstd = rsqrtf(var + LN_EPS);
                    al[idx] = bcast2(rstd);
                    de[idx] = bcast2(-mu * rstd);
                }
        }
        float bias = b2[r];

        // ---- pass 2: score, 2 slots/iter, 8 independent acc chains ----
        ull accA[4] = {0ull, 0ull, 0ull, 0ull};
        ull accB[4] = {0ull, 0ull, 0ull, 0ull};
        const ulonglong2* pg  = reinterpret_cast<const ulonglong2*>(sg);
        const ulonglong2* pbe = reinterpret_cast<const ulonglong2*>(sbe);
        const ulonglong2* pw  = reinterpret_cast<const ulonglong2*>(sw);
#pragma unroll 2
        for (int c = 0; c < HH / 4; c += 2) {
            ulonglong2 Aa[2], Ba[2], Ab[2], Bb[2];
#pragma unroll
            for (int p = 0; p < 2; p++) { Aa[p] = pA[p][c]; Ab[p] = pA[p][c + 1]; }
#pragma unroll
            for (int q = 0; q < 2; q++) { Ba[q] = pB[q][c]; Bb[q] = pB[q][c + 1]; }
            ulonglong2 Ga = pg[c],  BEa = pbe[c],  Wa = pw[c];
            ulonglong2 Gb = pg[c+1], BEb = pbe[c+1], Wb = pw[c+1];
#pragma unroll
            for (int p = 0; p < 2; p++)
#pragma unroll
                for (int q = 0; q < 2; q++) {
                    int idx = p * 2 + q;
                    ull h, t;
                    h = add2(Aa[p].x, Ba[q].x);
                    t = fma2(h, al[idx], de[idx]);
                    t = fma2(t, Ga.x, BEa.x);
                    t = relu2(t);
                    accA[idx] = fma2(t, Wa.x, accA[idx]);
                    h = add2(Aa[p].y, Ba[q].y);
                    t = fma2(h, al[idx], de[idx]);
                    t = fma2(t, Ga.y, BEa.y);
                    t = relu2(t);
                    accA[idx] = fma2(t, Wa.y, accA[idx]);
                    h = add2(Ab[p].x, Bb[q].x);
                    t = fma2(h, al[idx], de[idx]);
                    t = fma2(t, Gb.x, BEb.x);
                    t = relu2(t);
                    accB[idx] = fma2(t, Wb.x, accB[idx]);
                    h = add2(Ab[p].y, Bb[q].y);
                    t = fma2(h, al[idx], de[idx]);
                    t = fma2(t, Gb.y, BEb.y);
                    t = relu2(t);
                    accB[idx] = fma2(t, Wb.y, accB[idx]);
                }
        }

#pragma unroll
        for (int p = 0; p < 4; p++) {
            float sc = sum2(add2(accA[p], accB[p])) + bias;
            if (sc > best[p]) { best[p] = sc; bestr[p] = r; }
        }
    }

    // Output layout (float32): [x | best_score | best_rel | edge_mask]
    float* oscore = out + NN * FF;
    float* orel   = oscore + NN * NN;
    float* omask  = orel + NN * NN;
#pragma unroll
    for (int p = 0; p < 2; p++)
#pragma unroll
        for (int q = 0; q < 2; q++) {
            int idx = p * 2 + q;
            int gi = bi0 + ty + 32 * p;
            int gj = bj0 + tx + 16 * q;
            size_t o = (size_t)gi * NN + gj;
            oscore[o] = best[idx];
            orel[o]   = (float)bestr[idx];
            omask[o]  = (gi != gj && best[idx] > THRESH) ? 1.f : 0.f;
        }
}

// ---------------------------------------------------------------------------
// launch
// ---------------------------------------------------------------------------
extern "C" void kernel_launch(void* const* d_in, const int* in_sizes, int n_in,
                              void* d_out, int out_size) {
    const float* img   = (const float*)d_in[0];
    const float* txt   = (const float*)d_in[1];
    const float* W1    = (const float*)d_in[2];
    const float* b1    = (const float*)d_in[3];
    const float* gamma = (const float*)d_in[4];
    const float* beta  = (const float*)d_in[5];
    const float* w2    = (const float*)d_in[6];
    const float* b2    = (const float*)d_in[7];
    float* out = (float*)d_out;

    cudaFuncSetAttribute(pairwise_kernel,
                         cudaFuncAttributeMaxDynamicSharedMemorySize, PSMEM_BYTES);

    concat_kernel<<<(NN * FF / 4 + 255) / 256, 256>>>(img, txt, out);

    dim3 ggrid(HH / 128, NN / 128, RR * 2);
    gemm_ab<<<ggrid, 256>>>(out, W1, b1);

    rowsumsq_kernel<<<RR * NN * 2 * 32 / 256, 256>>>();

    dim3 pgrid(NN / PBJ, NN / PBI);
    pairwise_kernel<<<pgrid, PTHREADS, PSMEM_BYTES>>>(gamma, beta, w2, b2, out);
}

// round 12
// speedup vs baseline: 1.2915x; 1.2915x over previous
#include <cuda_runtime.h>
#include <math.h>

#define NN 512          // total nodes
#define FF 512          // feature dim
#define HH 512          // hidden dim
#define RR 4            // relations
#define LN_EPS 1e-5f
#define THRESH 0.2f

typedef unsigned long long ull;

// Scratch (device globals: no allocation allowed in kernel_launch)
__device__ float g_a[RR][NN][HH];   // x @ Wl[r]^T + b1[r]
__device__ float g_b[RR][NN][HH];   // x @ Wr[r]^T
__device__ float g_sa[RR][NN];      // row sums of g_a
__device__ float g_qa[RR][NN];      // row sumsq of g_a
__device__ float g_sb[RR][NN];      // row sums of g_b
__device__ float g_qb[RR][NN];      // row sumsq of g_b
__device__ float g_P[RR][HH];       // gamma * w2 (fast path)
__device__ int   g_flag;            // 1 if beta==0 && gamma>0 everywhere

// ---------------------------------------------------------------------------
// packed f32x2 helpers
// ---------------------------------------------------------------------------
__device__ __forceinline__ ull add2(ull a, ull b) {
    ull d; asm("add.rn.f32x2 %0,%1,%2;" : "=l"(d) : "l"(a), "l"(b)); return d;
}
__device__ __forceinline__ ull fma2(ull a, ull b, ull c) {
    ull d; asm("fma.rn.f32x2 %0,%1,%2,%3;" : "=l"(d) : "l"(a), "l"(b), "l"(c)); return d;
}
__device__ __forceinline__ ull bcast2(float x) {
    ull d; unsigned u = __float_as_uint(x);
    asm("mov.b64 %0,{%1,%1};" : "=l"(d) : "r"(u)); return d;
}
__device__ __forceinline__ float sum2(ull v) {
    unsigned lo, hi;
    asm("mov.b64 {%0,%1},%2;" : "=r"(lo), "=r"(hi) : "l"(v));
    return __uint_as_float(lo) + __uint_as_float(hi);
}
__device__ __forceinline__ ull relu2(ull v) {
    unsigned lo, hi;
    asm("mov.b64 {%0,%1},%2;" : "=r"(lo), "=r"(hi) : "l"(v));
    float flo = fmaxf(__uint_as_float(lo), 0.f);
    float fhi = fmaxf(__uint_as_float(hi), 0.f);
    ull d;
    asm("mov.b64 %0,{%1,%2};" : "=l"(d) : "r"(__float_as_uint(flo)), "r"(__float_as_uint(fhi)));
    return d;
}

// ---------------------------------------------------------------------------
// Kernel 0: concat feats_img/feats_txt into out[0 : NN*FF]
// ---------------------------------------------------------------------------
__global__ void concat_kernel(const float* __restrict__ img,
                              const float* __restrict__ txt,
                              float* __restrict__ out) {
    int idx = blockIdx.x * blockDim.x + threadIdx.x;
    const int HALF = 256 * FF / 4;
    float4 v;
    if (idx < HALF) v = reinterpret_cast<const float4*>(img)[idx];
    else            v = reinterpret_cast<const float4*>(txt)[idx - HALF];
    reinterpret_cast<float4*>(out)[idx] = v;
}

// ---------------------------------------------------------------------------
// Kernel 0b: prep — P = gamma*w2, flag = (beta==0 && gamma>0 everywhere)
// ---------------------------------------------------------------------------
__global__ __launch_bounds__(512) void prep_kernel(const float* __restrict__ gamma,
                                                   const float* __restrict__ beta,
                                                   const float* __restrict__ w2) {
    __shared__ float smx[16], smn[16];
    const int tid = threadIdx.x;
    float mx = 0.f, mn = 1e30f;
    float* P = &g_P[0][0];
#pragma unroll
    for (int e = tid; e < RR * HH; e += 512) {
        float be = beta[e], g = gamma[e];
        mx = fmaxf(mx, fabsf(be));
        mn = fminf(mn, g);
        P[e] = g * w2[e];
    }
#pragma unroll
    for (int o = 16; o > 0; o >>= 1) {
        mx = fmaxf(mx, __shfl_xor_sync(0xffffffffu, mx, o));
        mn = fminf(mn, __shfl_xor_sync(0xffffffffu, mn, o));
    }
    if ((tid & 31) == 0) { smx[tid >> 5] = mx; smn[tid >> 5] = mn; }
    __syncthreads();
    if (tid == 0) {
        float fmx = 0.f, fmn = 1e30f;
#pragma unroll
        for (int w = 0; w < 16; w++) { fmx = fmaxf(fmx, smx[w]); fmn = fminf(fmn, smn[w]); }
        g_flag = (fmx == 0.f && fmn > 0.f) ? 1 : 0;
    }
}

// ---------------------------------------------------------------------------
// Kernel 1: projection SGEMM (BM=BN=128, BK=8, 8x8/thread, packed f32x2),
// double-buffered smem, one sync per k-step.
// ---------------------------------------------------------------------------
__global__ __launch_bounds__(256) void gemm_ab(const float* __restrict__ x,
                                               const float* __restrict__ W1,
                                               const float* __restrict__ b1) {
    const int r    = blockIdx.z >> 1;
    const int side = blockIdx.z & 1;
    const float* B = W1 + (size_t)r * HH * (2 * FF) + side * FF;
    float* outp = side ? &g_b[r][0][0] : &g_a[r][0][0];

    const int bi = blockIdx.y * 128;
    const int bh = blockIdx.x * 128;

    __shared__ __align__(16) float As[2][8][128];
    __shared__ __align__(16) float Bs[2][8][128];

    const int tid  = threadIdx.x;
    const int lrow = tid >> 1;
    const int lcol = (tid & 1) << 2;
    const int ty   = tid >> 4;
    const int tx   = tid & 15;

    const float* aptr = x + (size_t)(bi + lrow) * FF + lcol;
    const float* bptr = B + (size_t)(bh + lrow) * (2 * FF) + lcol;

    ull acc2[8][4];
#pragma unroll
    for (int m = 0; m < 8; m++)
#pragma unroll
        for (int n = 0; n < 4; n++) acc2[m][n] = 0ull;

    {
        float4 av = *reinterpret_cast<const float4*>(aptr);
        float4 bv = *reinterpret_cast<const float4*>(bptr);
        As[0][lcol + 0][lrow] = av.x; As[0][lcol + 1][lrow] = av.y;
        As[0][lcol + 2][lrow] = av.z; As[0][lcol + 3][lrow] = av.w;
        Bs[0][lcol + 0][lrow] = bv.x; Bs[0][lcol + 1][lrow] = bv.y;
        Bs[0][lcol + 2][lrow] = bv.z; Bs[0][lcol + 3][lrow] = bv.w;
    }
    __syncthreads();

#pragma unroll 1
    for (int k0 = 0; k0 < FF / 8; k0++) {
        const int cur = k0 & 1;
        float4 av, bv;
        if (k0 < FF / 8 - 1) {
            av = *reinterpret_cast<const float4*>(aptr + (k0 + 1) * 8);
            bv = *reinterpret_cast<const float4*>(bptr + (k0 + 1) * 8);
        }
#pragma unroll
        for (int kk = 0; kk < 8; kk++) {
            float4 a0 = *reinterpret_cast<const float4*>(&As[cur][kk][ty * 8]);
            float4 a1 = *reinterpret_cast<const float4*>(&As[cur][kk][ty * 8 + 4]);
            ulonglong2 b0 = *reinterpret_cast<const ulonglong2*>(&Bs[cur][kk][tx * 8]);
            ulonglong2 b1v = *reinterpret_cast<const ulonglong2*>(&Bs[cur][kk][tx * 8 + 4]);
            ull rb2[4] = {b0.x, b0.y, b1v.x, b1v.y};
            float ra[8] = {a0.x, a0.y, a0.z, a0.w, a1.x, a1.y, a1.z, a1.w};
#pragma unroll
            for (int m = 0; m < 8; m++) {
                ull ra2 = bcast2(ra[m]);
#pragma unroll
                for (int n = 0; n < 4; n++)
                    acc2[m][n] = fma2(ra2, rb2[n], acc2[m][n]);
            }
        }
        if (k0 < FF / 8 - 1) {
            const int nxt = cur ^ 1;
            As[nxt][lcol + 0][lrow] = av.x; As[nxt][lcol + 1][lrow] = av.y;
            As[nxt][lcol + 2][lrow] = av.z; As[nxt][lcol + 3][lrow] = av.w;
            Bs[nxt][lcol + 0][lrow] = bv.x; Bs[nxt][lcol + 1][lrow] = bv.y;
            Bs[nxt][lcol + 2][lrow] = bv.z; Bs[nxt][lcol + 3][lrow] = bv.w;
        }
        __syncthreads();
    }

    ull bias2[4];
    if (side) {
#pragma unroll
        for (int n = 0; n < 4; n++) bias2[n] = 0ull;
    } else {
        const ull* bp = reinterpret_cast<const ull*>(b1 + r * HH + bh + tx * 8);
#pragma unroll
        for (int n = 0; n < 4; n++) bias2[n] = bp[n];
    }
#pragma unroll
    for (int m = 0; m < 8; m++) {
        ull* orow = reinterpret_cast<ull*>(outp + (size_t)(bi + ty * 8 + m) * HH + bh + tx * 8);
#pragma unroll
        for (int n = 0; n < 4; n++)
            orow[n] = add2(acc2[m][n], bias2[n]);
    }
}

// ---------------------------------------------------------------------------
// Kernel 1b: row sums + sums of squares of g_a / g_b (one warp per row).
// ---------------------------------------------------------------------------
__global__ __launch_bounds__(256) void rowsumsq_kernel() {
    int gw   = (blockIdx.x * 256 + threadIdx.x) >> 5;   // 0..4095
    int lane = threadIdx.x & 31;
    int side = gw >> 11;            // 0: a, 1: b
    int rem  = gw & 2047;           // r*NN + node
    const float* base = side ? &g_b[0][0][0] : &g_a[0][0][0];
    const float* row  = base + (size_t)rem * HH;

    float s = 0.f, q = 0.f;
#pragma unroll
    for (int c = 0; c < 4; c++) {
        float4 v = *reinterpret_cast<const float4*>(row + c * 128 + lane * 4);
        s += (v.x + v.y) + (v.z + v.w);
        q = fmaf(v.x, v.x, q); q = fmaf(v.y, v.y, q);
        q = fmaf(v.z, v.z, q); q = fmaf(v.w, v.w, q);
    }
#pragma unroll
    for (int o = 16; o > 0; o >>= 1) {
        s += __shfl_xor_sync(0xffffffffu, s, o);
        q += __shfl_xor_sync(0xffffffffu, q, o);
    }
    if (lane == 0) {
        if (side) { g_sb[0][rem] = s; g_qb[0][rem] = q; }
        else      { g_sa[0][rem] = s; g_qa[0][rem] = q; }
    }
}

// ---------------------------------------------------------------------------
// Kernel 2: pairwise LN-MLP + argmax. Tile 64i x 32j, 512 threads (32x16),
// thread owns 2i x 2j = 4 pairs.
// FAST path (beta==0 && gamma>0): single pass per r,
//   q2 += h^2;  acc += relu(h - mu) * P   (P = gamma*w2)
//   score = rstd * acc + b2, rstd from q2 closed-form. No cross-term pass.
// GENERAL path: two passes (cross terms, then normalized score).
// ---------------------------------------------------------------------------
#define PBI 64
#define PBJ 32
#define PPAD 4
#define PST (HH + PPAD)        // 516 floats per row
#define PSMEM_FLOATS ((PBI + PBJ) * PST + 3 * (HH + 4) + 4)
#define PSMEM_BYTES (PSMEM_FLOATS * 4)
#define PTHREADS 512

__global__ __launch_bounds__(PTHREADS) void pairwise_kernel(
        const float* __restrict__ gamma, const float* __restrict__ beta,
        const float* __restrict__ w2,    const float* __restrict__ b2,
        float* __restrict__ out) {
    extern __shared__ __align__(16) float sm[];
    float* sa  = sm;                        // PBI * PST
    float* sb  = sa + PBI * PST;            // PBJ * PST
    float* sg  = sb + PBJ * PST;            // HH + 4
    float* sbe = sg + (HH + 4);             // HH + 4
    float* sw  = sbe + (HH + 4);            // HH + 4

    const int tid = threadIdx.x;
    const int tx  = tid & 15;           // j base (0..15)
    const int ty  = tid >> 4;           // i base (0..31)
    const int bi0 = blockIdx.y * PBI;
    const int bj0 = blockIdx.x * PBJ;
    const bool fast = (g_flag != 0);

    float best[4];
    int   bestr[4];
#pragma unroll
    for (int p = 0; p < 4; p++) { best[p] = -1e30f; bestr[p] = 0; }

    const float inv_h = 1.f / (float)HH;

#pragma unroll 1
    for (int r = 0; r < RR; r++) {
        __syncthreads();
        // stage tiles: (PBI+PBJ)*HH/4 = 12288 float4 over 512 threads
        for (int t = tid; t < (PBI + PBJ) * (HH / 4); t += PTHREADS) {
            int row = t >> 7;
            int c4  = t & 127;
            float4 v;
            float* dst;
            if (row < PBI) {
                v = reinterpret_cast<const float4*>(&g_a[r][bi0 + row][0])[c4];
                dst = &sa[row * PST];
            } else {
                v = reinterpret_cast<const float4*>(&g_b[r][bj0 + row - PBI][0])[c4];
                dst = &sb[(row - PBI) * PST];
            }
            reinterpret_cast<float4*>(dst)[c4] = v;
        }
        if (fast) {
            if (tid < HH / 4) {
                reinterpret_cast<float4*>(sw)[tid] =
                    reinterpret_cast<const float4*>(&g_P[r][0])[tid];
            }
        } else if (tid < 3 * HH / 4) {
            int arr = tid >> 7;
            int c4  = tid & 127;
            const float* src = (arr == 0) ? gamma : (arr == 1) ? beta : w2;
            float* dst = (arr == 0) ? sg : (arr == 1) ? sbe : sw;
            reinterpret_cast<float4*>(dst)[c4] =
                reinterpret_cast<const float4*>(src + r * HH)[c4];
        }
        __syncthreads();

        const ulonglong2* pA[2];
        const ulonglong2* pB[2];
#pragma unroll
        for (int p = 0; p < 2; p++)
            pA[p] = reinterpret_cast<const ulonglong2*>(&sa[(ty + 32 * p) * PST]);
#pragma unroll
        for (int q = 0; q < 2; q++)
            pB[q] = reinterpret_cast<const ulonglong2*>(&sb[(tx + 16 * q) * PST]);

        float SA[2], SB[2];
#pragma unroll
        for (int p = 0; p < 2; p++) SA[p] = g_sa[r][bi0 + ty + 32 * p];
#pragma unroll
        for (int q = 0; q < 2; q++) SB[q] = g_sb[r][bj0 + tx + 16 * q];
        float bias = b2[r];

        if (fast) {
            // ---------------- FAST: single pass ----------------
            float mus[4];
            ull negmu[4];
#pragma unroll
            for (int p = 0; p < 2; p++)
#pragma unroll
                for (int q = 0; q < 2; q++) {
                    int idx = p * 2 + q;
                    float mu = (SA[p] + SB[q]) * inv_h;
                    mus[idx] = mu;
                    negmu[idx] = bcast2(-mu);
                }

            ull q2s[4]  = {0ull, 0ull, 0ull, 0ull};
            ull accA[4] = {0ull, 0ull, 0ull, 0ull};
            ull accB[4] = {0ull, 0ull, 0ull, 0ull};
            const ulonglong2* pw = reinterpret_cast<const ulonglong2*>(sw);

#pragma unroll 2
            for (int c = 0; c < HH / 4; c += 2) {
                ulonglong2 Aa[2], Ba[2], Ab[2], Bb[2];
#pragma unroll
                for (int p = 0; p < 2; p++) { Aa[p] = pA[p][c]; Ab[p] = pA[p][c + 1]; }
#pragma unroll
                for (int q = 0; q < 2; q++) { Ba[q] = pB[q][c]; Bb[q] = pB[q][c + 1]; }
                ulonglong2 Wa = pw[c], Wb = pw[c + 1];
#pragma unroll
                for (int p = 0; p < 2; p++)
#pragma unroll
                    for (int q = 0; q < 2; q++) {
                        int idx = p * 2 + q;
                        ull h, t;
                        h = add2(Aa[p].x, Ba[q].x);
                        q2s[idx] = fma2(h, h, q2s[idx]);
                        t = add2(h, negmu[idx]);
                        t = relu2(t);
                        accA[idx] = fma2(t, Wa.x, accA[idx]);
                        h = add2(Aa[p].y, Ba[q].y);
                        q2s[idx] = fma2(h, h, q2s[idx]);
                        t = add2(h, negmu[idx]);
                        t = relu2(t);
                        accA[idx] = fma2(t, Wa.y, accA[idx]);
                        h = add2(Ab[p].x, Bb[q].x);
                        q2s[idx] = fma2(h, h, q2s[idx]);
                        t = add2(h, negmu[idx]);
                        t = relu2(t);
                        accB[idx] = fma2(t, Wb.x, accB[idx]);
                        h = add2(Ab[p].y, Bb[q].y);
                        q2s[idx] = fma2(h, h, q2s[idx]);
                        t = add2(h, negmu[idx]);
                        t = relu2(t);
                        accB[idx] = fma2(t, Wb.y, accB[idx]);
                    }
            }

#pragma unroll
            for (int idx = 0; idx < 4; idx++) {
                float q2  = sum2(q2s[idx]);
                float mu  = mus[idx];
                float var = fmaf(-mu, mu, q2 * inv_h);
                float rstd = rsqrtf(var + LN_EPS);
                float sc = fmaf(sum2(add2(accA[idx], accB[idx])), rstd, bias);
                if (sc > best[idx]) { best[idx] = sc; bestr[idx] = r; }
            }
        } else {
            // ---------------- GENERAL: two passes ----------------
            float QA[2], QB[2];
#pragma unroll
            for (int p = 0; p < 2; p++) QA[p] = g_qa[r][bi0 + ty + 32 * p];
#pragma unroll
            for (int q = 0; q < 2; q++) QB[q] = g_qb[r][bj0 + tx + 16 * q];

            ull crA[4] = {0ull, 0ull, 0ull, 0ull};
            ull crB[4] = {0ull, 0ull, 0ull, 0ull};
#pragma unroll 2
            for (int c = 0; c < HH / 4; c += 2) {
                ulonglong2 Aa[2], Ba[2], Ab[2], Bb[2];
#pragma unroll
                for (int p = 0; p < 2; p++) { Aa[p] = pA[p][c]; Ab[p] = pA[p][c + 1]; }
#pragma unroll
                for (int q = 0; q < 2; q++) { Ba[q] = pB[q][c]; Bb[q] = pB[q][c + 1]; }
#pragma unroll
                for (int p = 0; p < 2; p++)
#pragma unroll
                    for (int q = 0; q < 2; q++) {
                        int idx = p * 2 + q;
                        crA[idx] = fma2(Aa[p].x, Ba[q].x, crA[idx]);
                        crA[idx] = fma2(Aa[p].y, Ba[q].y, crA[idx]);
                        crB[idx] = fma2(Ab[p].x, Bb[q].x, crB[idx]);
                        crB[idx] = fma2(Ab[p].y, Bb[q].y, crB[idx]);
                    }
            }

            ull al[4], de[4];
#pragma unroll
            for (int p = 0; p < 2; p++)
#pragma unroll
                for (int q = 0; q < 2; q++) {
                    int idx = p * 2 + q;
                    float cross = sum2(add2(crA[idx], crB[idx]));
                    float mu  = (SA[p] + SB[q]) * inv_h;
                    float e2  = fmaf(2.f, cross, QA[p] + QB[q]) * inv_h;
                    float var = fmaf(-mu, mu, e2);
                    float rstd = rsqrtf(var + LN_EPS);
                    al[idx] = bcast2(rstd);
                    de[idx] = bcast2(-mu * rstd);
                }

            ull accA[4] = {0ull, 0ull, 0ull, 0ull};
            ull accB[4] = {0ull, 0ull, 0ull, 0ull};
            const ulonglong2* pg  = reinterpret_cast<const ulonglong2*>(sg);
            const ulonglong2* pbe = reinterpret_cast<const ulonglong2*>(sbe);
            const ulonglong2* pw  = reinterpret_cast<const ulonglong2*>(sw);
#pragma unroll 2
            for (int c = 0; c < HH / 4; c += 2) {
                ulonglong2 Aa[2], Ba[2], Ab[2], Bb[2];
#pragma unroll
                for (int p = 0; p < 2; p++) { Aa[p] = pA[p][c]; Ab[p] = pA[p][c + 1]; }
#pragma unroll
                for (int q = 0; q < 2; q++) { Ba[q] = pB[q][c]; Bb[q] = pB[q][c + 1]; }
                ulonglong2 Ga = pg[c],  BEa = pbe[c],  Wa = pw[c];
                ulonglong2 Gb = pg[c+1], BEb = pbe[c+1], Wb = pw[c+1];
#pragma unroll
                for (int p = 0; p < 2; p++)
#pragma unroll
                    for (int q = 0; q < 2; q++) {
                        int idx = p * 2 + q;
                        ull h, t;
                        h = add2(Aa[p].x, Ba[q].x);
                        t = fma2(h, al[idx], de[idx]);
                        t = fma2(t, Ga.x, BEa.x);
                        t = relu2(t);
                        accA[idx] = fma2(t, Wa.x, accA[idx]);
                        h = add2(Aa[p].y, Ba[q].y);
                        t = fma2(h, al[idx], de[idx]);
                        t = fma2(t, Ga.y, BEa.y);
                        t = relu2(t);
                        accA[idx] = fma2(t, Wa.y, accA[idx]);
                        h = add2(Ab[p].x, Bb[q].x);
                        t = fma2(h, al[idx], de[idx]);
                        t = fma2(t, Gb.x, BEb.x);
                        t = relu2(t);
                        accB[idx] = fma2(t, Wb.x, accB[idx]);
                        h = add2(Ab[p].y, Bb[q].y);
                        t = fma2(h, al[idx], de[idx]);
                        t = fma2(t, Gb.y, BEb.y);
                        t = relu2(t);
                        accB[idx] = fma2(t, Wb.y, accB[idx]);
                    }
            }

#pragma unroll
            for (int p = 0; p < 4; p++) {
                float sc = sum2(add2(accA[p], accB[p])) + bias;
                if (sc > best[p]) { best[p] = sc; bestr[p] = r; }
            }
        }
    }

    // Output layout (float32): [x | best_score | best_rel | edge_mask]
    float* oscore = out + NN * FF;
    float* orel   = oscore + NN * NN;
    float* omask  = orel + NN * NN;
#pragma unroll
    for (int p = 0; p < 2; p++)
#pragma unroll
        for (int q = 0; q < 2; q++) {
            int idx = p * 2 + q;
            int gi = bi0 + ty + 32 * p;
            int gj = bj0 + tx + 16 * q;
            size_t o = (size_t)gi * NN + gj;
            oscore[o] = best[idx];
            orel[o]   = (float)bestr[idx];
            omask[o]  = (gi != gj && best[idx] > THRESH) ? 1.f : 0.f;
        }
}

// ---------------------------------------------------------------------------
// launch
// ---------------------------------------------------------------------------
extern "C" void kernel_launch(void* const* d_in, const int* in_sizes, int n_in,
                              void* d_out, int out_size) {
    const float* img   = (const float*)d_in[0];
    const float* txt   = (const float*)d_in[1];
    const float* W1    = (const float*)d_in[2];
    const float* b1    = (const float*)d_in[3];
    const float* gamma = (const float*)d_in[4];
    const float* beta  = (const float*)d_in[5];
    const float* w2    = (const float*)d_in[6];
    const float* b2    = (const float*)d_in[7];
    float* out = (float*)d_out;

    cudaFuncSetAttribute(pairwise_kernel,
                         cudaFuncAttributeMaxDynamicSharedMemorySize, PSMEM_BYTES);

    concat_kernel<<<(NN * FF / 4 + 255) / 256, 256>>>(img, txt, out);

    prep_kernel<<<1, 512>>>(gamma, beta, w2);

    dim3 ggrid(HH / 128, NN / 128, RR * 2);
    gemm_ab<<<ggrid, 256>>>(out, W1, b1);

    rowsumsq_kernel<<<RR * NN * 2 * 32 / 256, 256>>>();

    dim3 pgrid(NN / PBJ, NN / PBI);
    pairwise_kernel<<<pgrid, PTHREADS, PSMEM_BYTES>>>(gamma, beta, w2, b2, out);
}

// round 14
// speedup vs baseline: 1.3824x; 1.0704x over previous
#include <cuda_runtime.h>
#include <math.h>

#define NN 512          // total nodes
#define FF 512          // feature dim
#define HH 512          // hidden dim
#define RR 4            // relations
#define LN_EPS 1e-5f
#define THRESH 0.2f

typedef unsigned long long ull;

// Scratch (device globals: no allocation allowed in kernel_launch)
__device__ float g_a[RR][NN][HH];   // centered: x@Wl^T + b1 - rowmean
__device__ float g_b[RR][NN][HH];   // centered: x@Wr^T - rowmean
__device__ float g_qa[RR][NN];      // centered row sumsq of g_a
__device__ float g_qb[RR][NN];      // centered row sumsq of g_b
__device__ float g_P[RR][HH];       // gamma * w2 (fast path)
__device__ int   g_flag;            // 1 if beta==0 && gamma>0 everywhere

// ---------------------------------------------------------------------------
// packed f32x2 helpers
// ---------------------------------------------------------------------------
__device__ __forceinline__ ull add2(ull a, ull b) {
    ull d; asm("add.rn.f32x2 %0,%1,%2;" : "=l"(d) : "l"(a), "l"(b)); return d;
}
__device__ __forceinline__ ull mul2(ull a, ull b) {
    ull d; asm("mul.rn.f32x2 %0,%1,%2;" : "=l"(d) : "l"(a), "l"(b)); return d;
}
__device__ __forceinline__ ull fma2(ull a, ull b, ull c) {
    ull d; asm("fma.rn.f32x2 %0,%1,%2,%3;" : "=l"(d) : "l"(a), "l"(b), "l"(c)); return d;
}
__device__ __forceinline__ ull bcast2(float x) {
    ull d; unsigned u = __float_as_uint(x);
    asm("mov.b64 %0,{%1,%1};" : "=l"(d) : "r"(u)); return d;
}
__device__ __forceinline__ float sum2(ull v) {
    unsigned lo, hi;
    asm("mov.b64 {%0,%1},%2;" : "=r"(lo), "=r"(hi) : "l"(v));
    return __uint_as_float(lo) + __uint_as_float(hi);
}
__device__ __forceinline__ ull relu2(ull v) {
    unsigned lo, hi;
    asm("mov.b64 {%0,%1},%2;" : "=r"(lo), "=r"(hi) : "l"(v));
    float flo = fmaxf(__uint_as_float(lo), 0.f);
    float fhi = fmaxf(__uint_as_float(hi), 0.f);
    ull d;
    asm("mov.b64 %0,{%1,%2};" : "=l"(d) : "r"(__float_as_uint(flo)), "r"(__float_as_uint(fhi)));
    return d;
}

// ---------------------------------------------------------------------------
// Kernel 0: concat feats_img/feats_txt into out[0 : NN*FF]
// ---------------------------------------------------------------------------
__global__ void concat_kernel(const float* __restrict__ img,
                              const float* __restrict__ txt,
                              float* __restrict__ out) {
    int idx = blockIdx.x * blockDim.x + threadIdx.x;
    const int HALF = 256 * FF / 4;
    float4 v;
    if (idx < HALF) v = reinterpret_cast<const float4*>(img)[idx];
    else            v = reinterpret_cast<const float4*>(txt)[idx - HALF];
    reinterpret_cast<float4*>(out)[idx] = v;
}

// ---------------------------------------------------------------------------
// Kernel 0b: prep — P = gamma*w2, flag = (beta==0 && gamma>0 everywhere)
// ---------------------------------------------------------------------------
__global__ __launch_bounds__(512) void prep_kernel(const float* __restrict__ gamma,
                                                   const float* __restrict__ beta,
                                                   const float* __restrict__ w2) {
    __shared__ float smx[16], smn[16];
    const int tid = threadIdx.x;
    float mx = 0.f, mn = 1e30f;
    float* P = &g_P[0][0];
#pragma unroll
    for (int e = tid; e < RR * HH; e += 512) {
        float be = beta[e], g = gamma[e];
        mx = fmaxf(mx, fabsf(be));
        mn = fminf(mn, g);
        P[e] = g * w2[e];
    }
#pragma unroll
    for (int o = 16; o > 0; o >>= 1) {
        mx = fmaxf(mx, __shfl_xor_sync(0xffffffffu, mx, o));
        mn = fminf(mn, __shfl_xor_sync(0xffffffffu, mn, o));
    }
    if ((tid & 31) == 0) { smx[tid >> 5] = mx; smn[tid >> 5] = mn; }
    __syncthreads();
    if (tid == 0) {
        float fmx = 0.f, fmn = 1e30f;
#pragma unroll
        for (int w = 0; w < 16; w++) { fmx = fmaxf(fmx, smx[w]); fmn = fminf(fmn, smn[w]); }
        g_flag = (fmx == 0.f && fmn > 0.f) ? 1 : 0;
    }
}

// ---------------------------------------------------------------------------
// Kernel 1: projection SGEMM (BM=BN=128, BK=8, 8x8/thread, packed f32x2),
// double-buffered smem, one sync per k-step.
// ---------------------------------------------------------------------------
__global__ __launch_bounds__(256) void gemm_ab(const float* __restrict__ x,
                                               const float* __restrict__ W1,
                                               const float* __restrict__ b1) {
    const int r    = blockIdx.z >> 1;
    const int side = blockIdx.z & 1;
    const float* B = W1 + (size_t)r * HH * (2 * FF) + side * FF;
    float* outp = side ? &g_b[r][0][0] : &g_a[r][0][0];

    const int bi = blockIdx.y * 128;
    const int bh = blockIdx.x * 128;

    __shared__ __align__(16) float As[2][8][128];
    __shared__ __align__(16) float Bs[2][8][128];

    const int tid  = threadIdx.x;
    const int lrow = tid >> 1;
    const int lcol = (tid & 1) << 2;
    const int ty   = tid >> 4;
    const int tx   = tid & 15;

    const float* aptr = x + (size_t)(bi + lrow) * FF + lcol;
    const float* bptr = B + (size_t)(bh + lrow) * (2 * FF) + lcol;

    ull acc2[8][4];
#pragma unroll
    for (int m = 0; m < 8; m++)
#pragma unroll
        for (int n = 0; n < 4; n++) acc2[m][n] = 0ull;

    {
        float4 av = *reinterpret_cast<const float4*>(aptr);
        float4 bv = *reinterpret_cast<const float4*>(bptr);
        As[0][lcol + 0][lrow] = av.x; As[0][lcol + 1][lrow] = av.y;
        As[0][lcol + 2][lrow] = av.z; As[0][lcol + 3][lrow] = av.w;
        Bs[0][lcol + 0][lrow] = bv.x; Bs[0][lcol + 1][lrow] = bv.y;
        Bs[0][lcol + 2][lrow] = bv.z; Bs[0][lcol + 3][lrow] = bv.w;
    }
    __syncthreads();

#pragma unroll 1
    for (int k0 = 0; k0 < FF / 8; k0++) {
        const int cur = k0 & 1;
        float4 av, bv;
        if (k0 < FF / 8 - 1) {
            av = *reinterpret_cast<const float4*>(aptr + (k0 + 1) * 8);
            bv = *reinterpret_cast<const float4*>(bptr + (k0 + 1) * 8);
        }
#pragma unroll
        for (int kk = 0; kk < 8; kk++) {
            float4 a0 = *reinterpret_cast<const float4*>(&As[cur][kk][ty * 8]);
            float4 a1 = *reinterpret_cast<const float4*>(&As[cur][kk][ty * 8 + 4]);
            ulonglong2 b0 = *reinterpret_cast<const ulonglong2*>(&Bs[cur][kk][tx * 8]);
            ulonglong2 b1v = *reinterpret_cast<const ulonglong2*>(&Bs[cur][kk][tx * 8 + 4]);
            ull rb2[4] = {b0.x, b0.y, b1v.x, b1v.y};
            float ra[8] = {a0.x, a0.y, a0.z, a0.w, a1.x, a1.y, a1.z, a1.w};
#pragma unroll
            for (int m = 0; m < 8; m++) {
                ull ra2 = bcast2(ra[m]);
#pragma unroll
                for (int n = 0; n < 4; n++)
                    acc2[m][n] = fma2(ra2, rb2[n], acc2[m][n]);
            }
        }
        if (k0 < FF / 8 - 1) {
            const int nxt = cur ^ 1;
            As[nxt][lcol + 0][lrow] = av.x; As[nxt][lcol + 1][lrow] = av.y;
            As[nxt][lcol + 2][lrow] = av.z; As[nxt][lcol + 3][lrow] = av.w;
            Bs[nxt][lcol + 0][lrow] = bv.x; Bs[nxt][lcol + 1][lrow] = bv.y;
            Bs[nxt][lcol + 2][lrow] = bv.z; Bs[nxt][lcol + 3][lrow] = bv.w;
        }
        __syncthreads();
    }

    ull bias2[4];
    if (side) {
#pragma unroll
        for (int n = 0; n < 4; n++) bias2[n] = 0ull;
    } else {
        const ull* bp = reinterpret_cast<const ull*>(b1 + r * HH + bh + tx * 8);
#pragma unroll
        for (int n = 0; n < 4; n++) bias2[n] = bp[n];
    }
#pragma unroll
    for (int m = 0; m < 8; m++) {
        ull* orow = reinterpret_cast<ull*>(outp + (size_t)(bi + ty * 8 + m) * HH + bh + tx * 8);
#pragma unroll
        for (int n = 0; n < 4; n++)
            orow[n] = add2(acc2[m][n], bias2[n]);
    }
}

// ---------------------------------------------------------------------------
// Kernel 1b: CENTER rows of g_a / g_b in place, store centered row sumsq.
// One warp per row; 16 floats (4 float4) per lane are register-resident.
// ---------------------------------------------------------------------------
__global__ __launch_bounds__(256) void center_kernel() {
    int gw   = (blockIdx.x * 256 + threadIdx.x) >> 5;   // 0..4095
    int lane = threadIdx.x & 31;
    int side = gw >> 11;            // 0: a, 1: b
    int rem  = gw & 2047;           // r*NN + node
    float* base = side ? &g_b[0][0][0] : &g_a[0][0][0];
    float* row  = base + (size_t)rem * HH;

    float4 v[4];
    float s = 0.f;
#pragma unroll
    for (int c = 0; c < 4; c++) {
        v[c] = *reinterpret_cast<const float4*>(row + c * 128 + lane * 4);
        s += (v[c].x + v[c].y) + (v[c].z + v[c].w);
    }
#pragma unroll
    for (int o = 16; o > 0; o >>= 1)
        s += __shfl_xor_sync(0xffffffffu, s, o);
    const float mean = s * (1.f / (float)HH);

    float q = 0.f;
#pragma unroll
    for (int c = 0; c < 4; c++) {
        v[c].x -= mean; v[c].y -= mean; v[c].z -= mean; v[c].w -= mean;
        q = fmaf(v[c].x, v[c].x, q); q = fmaf(v[c].y, v[c].y, q);
        q = fmaf(v[c].z, v[c].z, q); q = fmaf(v[c].w, v[c].w, q);
        *reinterpret_cast<float4*>(row + c * 128 + lane * 4) = v[c];
    }
#pragma unroll
    for (int o = 16; o > 0; o >>= 1)
        q += __shfl_xor_sync(0xffffffffu, q, o);
    if (lane == 0) {
        if (side) g_qb[0][rem] = q;
        else      g_qa[0][rem] = q;
    }
}

// ---------------------------------------------------------------------------
// Kernel 2: pairwise LN-MLP + argmax on CENTERED tiles.
// t = a'+b' = h - mu directly; var = sum(t^2)/H exactly.
// FAST path (beta==0, gamma>0): per packed pair only
//   t=add2; q2=fma2(t,t); acc=fma2(relu2(t),P)   (3 fma-pipe + 1 relu)
//   score = rstd * acc + b2.
// GENERAL path: pass1 cross' = sum a'b'; var=(QA'+QB'+2cross')/H;
//   pass2: hn = (t*rstd)*gamma + beta, relu, dot w2.
// Tile 64i x 32j, 512 threads (32x16), thread owns 2i x 2j = 4 pairs.
// ---------------------------------------------------------------------------
#define PBI 64
#define PBJ 32
#define PPAD 4
#define PST (HH + PPAD)        // 516 floats per row
#define PSMEM_FLOATS ((PBI + PBJ) * PST + 3 * (HH + 4) + 4)
#define PSMEM_BYTES (PSMEM_FLOATS * 4)
#define PTHREADS 512

__global__ __launch_bounds__(PTHREADS) void pairwise_kernel(
        const float* __restrict__ gamma, const float* __restrict__ beta,
        const float* __restrict__ w2,    const float* __restrict__ b2,
        float* __restrict__ out) {
    extern __shared__ __align__(16) float sm[];
    float* sa  = sm;                        // PBI * PST
    float* sb  = sa + PBI * PST;            // PBJ * PST
    float* sg  = sb + PBJ * PST;            // HH + 4
    float* sbe = sg + (HH + 4);             // HH + 4
    float* sw  = sbe + (HH + 4);            // HH + 4

    const int tid = threadIdx.x;
    const int tx  = tid & 15;           // j base (0..15)
    const int ty  = tid >> 4;           // i base (0..31)
    const int bi0 = blockIdx.y * PBI;
    const int bj0 = blockIdx.x * PBJ;
    const bool fast = (g_flag != 0);

    float best[4];
    int   bestr[4];
#pragma unroll
    for (int p = 0; p < 4; p++) { best[p] = -1e30f; bestr[p] = 0; }

    const float inv_h = 1.f / (float)HH;

#pragma unroll 1
    for (int r = 0; r < RR; r++) {
        __syncthreads();
        // stage tiles: (PBI+PBJ)*HH/4 = 12288 float4 over 512 threads
        for (int t = tid; t < (PBI + PBJ) * (HH / 4); t += PTHREADS) {
            int row = t >> 7;
            int c4  = t & 127;
            float4 v;
            float* dst;
            if (row < PBI) {
                v = reinterpret_cast<const float4*>(&g_a[r][bi0 + row][0])[c4];
                dst = &sa[row * PST];
            } else {
                v = reinterpret_cast<const float4*>(&g_b[r][bj0 + row - PBI][0])[c4];
                dst = &sb[(row - PBI) * PST];
            }
            reinterpret_cast<float4*>(dst)[c4] = v;
        }
        if (fast) {
            if (tid < HH / 4) {
                reinterpret_cast<float4*>(sw)[tid] =
                    reinterpret_cast<const float4*>(&g_P[r][0])[tid];
            }
        } else if (tid < 3 * HH / 4) {
            int arr = tid >> 7;
            int c4  = tid & 127;
            const float* src = (arr == 0) ? gamma : (arr == 1) ? beta : w2;
            float* dst = (arr == 0) ? sg : (arr == 1) ? sbe : sw;
            reinterpret_cast<float4*>(dst)[c4] =
                reinterpret_cast<const float4*>(src + r * HH)[c4];
        }
        __syncthreads();

        const ulonglong2* pA[2];
        const ulonglong2* pB[2];
#pragma unroll
        for (int p = 0; p < 2; p++)
            pA[p] = reinterpret_cast<const ulonglong2*>(&sa[(ty + 32 * p) * PST]);
#pragma unroll
        for (int q = 0; q < 2; q++)
            pB[q] = reinterpret_cast<const ulonglong2*>(&sb[(tx + 16 * q) * PST]);

        float bias = b2[r];

        if (fast) {
            // ---------------- FAST: single pass, centered ----------------
            ull q2A[4]  = {0ull, 0ull, 0ull, 0ull};
            ull q2B[4]  = {0ull, 0ull, 0ull, 0ull};
            ull accA[4] = {0ull, 0ull, 0ull, 0ull};
            ull accB[4] = {0ull, 0ull, 0ull, 0ull};
            const ulonglong2* pw = reinterpret_cast<const ulonglong2*>(sw);

#pragma unroll 2
            for (int c = 0; c < HH / 4; c += 2) {
                ulonglong2 Aa[2], Ba[2], Ab[2], Bb[2];
#pragma unroll
                for (int p = 0; p < 2; p++) { Aa[p] = pA[p][c]; Ab[p] = pA[p][c + 1]; }
#pragma unroll
                for (int q = 0; q < 2; q++) { Ba[q] = pB[q][c]; Bb[q] = pB[q][c + 1]; }
                ulonglong2 Wa = pw[c], Wb = pw[c + 1];
#pragma unroll
                for (int p = 0; p < 2; p++)
#pragma unroll
                    for (int q = 0; q < 2; q++) {
                        int idx = p * 2 + q;
                        ull t, u;
                        t = add2(Aa[p].x, Ba[q].x);
                        q2A[idx] = fma2(t, t, q2A[idx]);
                        u = relu2(t);
                        accA[idx] = fma2(u, Wa.x, accA[idx]);
                        t = add2(Aa[p].y, Ba[q].y);
                        q2A[idx] = fma2(t, t, q2A[idx]);
                        u = relu2(t);
                        accA[idx] = fma2(u, Wa.y, accA[idx]);
                        t = add2(Ab[p].x, Bb[q].x);
                        q2B[idx] = fma2(t, t, q2B[idx]);
                        u = relu2(t);
                        accB[idx] = fma2(u, Wb.x, accB[idx]);
                        t = add2(Ab[p].y, Bb[q].y);
                        q2B[idx] = fma2(t, t, q2B[idx]);
                        u = relu2(t);
                        accB[idx] = fma2(u, Wb.y, accB[idx]);
                    }
            }

#pragma unroll
            for (int idx = 0; idx < 4; idx++) {
                float q2  = sum2(add2(q2A[idx], q2B[idx]));
                float var = q2 * inv_h;
                float rstd = rsqrtf(var + LN_EPS);
                float sc = fmaf(sum2(add2(accA[idx], accB[idx])), rstd, bias);
                if (sc > best[idx]) { best[idx] = sc; bestr[idx] = r; }
            }
        } else {
            // ---------------- GENERAL: two passes, centered ----------------
            float QA[2], QB[2];
#pragma unroll
            for (int p = 0; p < 2; p++) QA[p] = g_qa[r][bi0 + ty + 32 * p];
#pragma unroll
            for (int q = 0; q < 2; q++) QB[q] = g_qb[r][bj0 + tx + 16 * q];

            ull crA[4] = {0ull, 0ull, 0ull, 0ull};
            ull crB[4] = {0ull, 0ull, 0ull, 0ull};
#pragma unroll 2
            for (int c = 0; c < HH / 4; c += 2) {
                ulonglong2 Aa[2], Ba[2], Ab[2], Bb[2];
#pragma unroll
                for (int p = 0; p < 2; p++) { Aa[p] = pA[p][c]; Ab[p] = pA[p][c + 1]; }
#pragma unroll
                for (int q = 0; q < 2; q++) { Ba[q] = pB[q][c]; Bb[q] = pB[q][c + 1]; }
#pragma unroll
                for (int p = 0; p < 2; p++)
#pragma unroll
                    for (int q = 0; q < 2; q++) {
                        int idx = p * 2 + q;
                        crA[idx] = fma2(Aa[p].x, Ba[q].x, crA[idx]);
                        crA[idx] = fma2(Aa[p].y, Ba[q].y, crA[idx]);
                        crB[idx] = fma2(Ab[p].x, Bb[q].x, crB[idx]);
                        crB[idx] = fma2(Ab[p].y, Bb[q].y, crB[idx]);
                    }
            }

            ull al[4];
#pragma unroll
            for (int p = 0; p < 2; p++)
#pragma unroll
                for (int q = 0; q < 2; q++) {
                    int idx = p * 2 + q;
                    float cross = sum2(add2(crA[idx], crB[idx]));
                    float var = fmaf(2.f, cross, QA[p] + QB[q]) * inv_h;
                    al[idx] = bcast2(rsqrtf(var + LN_EPS));
                }

            ull accA[4] = {0ull, 0ull, 0ull, 0ull};
            ull accB[4] = {0ull, 0ull, 0ull, 0ull};
            const ulonglong2* pg  = reinterpret_cast<const ulonglong2*>(sg);
            const ulonglong2* pbe = reinterpret_cast<const ulonglong2*>(sbe);
            const ulonglong2* pw  = reinterpret_cast<const ulonglong2*>(sw);
#pragma unroll 2
            for (int c = 0; c < HH / 4; c += 2) {
                ulonglong2 Aa[2], Ba[2], Ab[2], Bb[2];
#pragma unroll
                for (int p = 0; p < 2; p++) { Aa[p] = pA[p][c]; Ab[p] = pA[p][c + 1]; }
#pragma unroll
                for (int q = 0; q < 2; q++) { Ba[q] = pB[q][c]; Bb[q] = pB[q][c + 1]; }
                ulonglong2 Ga = pg[c],  BEa = pbe[c],  Wa = pw[c];
                ulonglong2 Gb = pg[c+1], BEb = pbe[c+1], Wb = pw[c+1];
#pragma unroll
                for (int p = 0; p < 2; p++)
#pragma unroll
                    for (int q = 0; q < 2; q++) {
                        int idx = p * 2 + q;
                        ull t, u;
                        t = add2(Aa[p].x, Ba[q].x);
                        t = mul2(t, al[idx]);
                        u = fma2(t, Ga.x, BEa.x);
                        u = relu2(u);
                        accA[idx] = fma2(u, Wa.x, accA[idx]);
                        t = add2(Aa[p].y, Ba[q].y);
                        t = mul2(t, al[idx]);
                        u = fma2(t, Ga.y, BEa.y);
                        u = relu2(u);
                        accA[idx] = fma2(u, Wa.y, accA[idx]);
                        t = add2(Ab[p].x, Bb[q].x);
                        t = mul2(t, al[idx]);
                        u = fma2(t, Gb.x, BEb.x);
                        u = relu2(u);
                        accB[idx] = fma2(u, Wb.x, accB[idx]);
                        t = add2(Ab[p].y, Bb[q].y);
                        t = mul2(t, al[idx]);
                        u = fma2(t, Gb.y, BEb.y);
                        u = relu2(u);
                        accB[idx] = fma2(u, Wb.y, accB[idx]);
                    }
            }

#pragma unroll
            for (int p = 0; p < 4; p++) {
                float sc = sum2(add2(accA[p], accB[p])) + bias;
                if (sc > best[p]) { best[p] = sc; bestr[p] = r; }
            }
        }
    }

    // Output layout (float32): [x | best_score | best_rel | edge_mask]
    float* oscore = out + NN * FF;
    float* orel   = oscore + NN * NN;
    float* omask  = orel + NN * NN;
#pragma unroll
    for (int p = 0; p < 2; p++)
#pragma unroll
        for (int q = 0; q < 2; q++) {
            int idx = p * 2 + q;
            int gi = bi0 + ty + 32 * p;
            int gj = bj0 + tx + 16 * q;
            size_t o = (size_t)gi * NN + gj;
            oscore[o] = best[idx];
            orel[o]   = (float)bestr[idx];
            omask[o]  = (gi != gj && best[idx] > THRESH) ? 1.f : 0.f;
        }
}

// ---------------------------------------------------------------------------
// launch
// ---------------------------------------------------------------------------
extern "C" void kernel_launch(void* const* d_in, const int* in_sizes, int n_in,
                              void* d_out, int out_size) {
    const float* img   = (const float*)d_in[0];
    const float* txt   = (const float*)d_in[1];
    const float* W1    = (const float*)d_in[2];
    const float* b1    = (const float*)d_in[3];
    const float* gamma = (const float*)d_in[4];
    const float* beta  = (const float*)d_in[5];
    const float* w2    = (const float*)d_in[6];
    const float* b2    = (const float*)d_in[7];
    float* out = (float*)d_out;

    cudaFuncSetAttribute(pairwise_kernel,
                         cudaFuncAttributeMaxDynamicSharedMemorySize, PSMEM_BYTES);

    concat_kernel<<<(NN * FF / 4 + 255) / 256, 256>>>(img, txt, out);

    prep_kernel<<<1, 512>>>(gamma, beta, w2);

    dim3 ggrid(HH / 128, NN / 128, RR * 2);
    gemm_ab<<<ggrid, 256>>>(out, W1, b1);

    center_kernel<<<RR * NN * 2 * 32 / 256, 256>>>();

    dim3 pgrid(NN / PBJ, NN / PBI);
    pairwise_kernel<<<pgrid, PTHREADS, PSMEM_BYTES>>>(gamma, beta, w2, b2, out);
}